// round 12
// baseline (speedup 1.0000x reference)
#include <cuda_runtime.h>
#include <cstdint>

#define MAX_NODES 100000
#define NODE_TB   1024
#define NODE_GRID 148   // 148*1024 = 151552 >= 100000, single wave, 1 node/thread
#define DEG_SCALE 512.0f
#define INV_SCALE (1.0f / 512.0f)

// Packed accumulator: acc[i].x = 512*deg + C4, acc[i].y = S4.
// |C4| <= deg <= ~90 << 256, so deg and C4 separate exactly via rintf.
struct Scratch {
    float2   acc[MAX_NODES];
    float    part[2];         // [0] pair_loss_sum, [1] n_pairs
    unsigned done;
};
__device__ Scratch g_s;

__device__ __forceinline__ void red_v2(float2* addr, float a, float b) {
    asm volatile("red.global.add.v2.f32 [%0], {%1, %2};"
                 :: "l"(addr), "f"(a), "f"(b)
                 : "memory");
}

__global__ void edge_kernel(const float* __restrict__ pos,
                            const int*   __restrict__ ei,
                            int E) {
    int e = blockIdx.x * blockDim.x + threadIdx.x;
    if (e >= E) return;
    int s = ei[e];
    int t = ei[E + e];
    float2 ps = __ldg((const float2*)pos + s);
    float2 pt = __ldg((const float2*)pos + t);
    float dx = pt.x - ps.x;
    float dy = pt.y - ps.y;
    float nrm = sqrtf(fmaf(dx, dx, dy * dy));
    float inv = 1.0f / fmaxf(nrm, 1e-8f);
    float u = dx * inv, v = dy * inv;
    // cos(2t) = u^2 - v^2 ; sin(2t) = 2uv ; double-angle again for 4t.
    float a = u * u - v * v;
    float b = 2.0f * u * v;
    float c4 = a * a - b * b;
    float s4 = 2.0f * a * b;
    // 4-theta terms invariant under d -> -d: identical payload to both endpoints.
    // Degree folded into the x channel as +DEG_SCALE.
    red_v2(&g_s.acc[s], DEG_SCALE + c4, s4);
    red_v2(&g_s.acc[t], DEG_SCALE + c4, s4);
}

__global__ __launch_bounds__(NODE_TB, 1)
void node_kernel(int n, float* __restrict__ out) {
    const int i = blockIdx.x * blockDim.x + threadIdx.x;

    float pl = 0.0f, np = 0.0f;
    if (i < n) {
        float2 acc = g_s.acc[i];
        float k  = rintf(acc.x * INV_SCALE);          // exact degree
        float c4 = fmaf(k, -DEG_SCALE, acc.x);        // C4 = x - 512*k
        float s4 = acc.y;
        // sum_{i<j}(dot^2 - dot^4) = (k^2 - C4^2 - S4^2)/16 (incl. 0.5 pair factor)
        pl = (k * k - (c4 * c4 + s4 * s4)) * 0.0625f;
        np = 0.5f * k * (k - 1.0f);
    }

    #pragma unroll
    for (int o = 16; o > 0; o >>= 1) {
        pl += __shfl_down_sync(0xffffffffu, pl, o);
        np += __shfl_down_sync(0xffffffffu, np, o);
    }
    __shared__ float s_pl[32];
    __shared__ float s_np[32];
    int lane = threadIdx.x & 31;
    int wid  = threadIdx.x >> 5;
    if (lane == 0) { s_pl[wid] = pl; s_np[wid] = np; }
    __syncthreads();
    if (wid == 0) {
        pl = s_pl[lane];
        np = s_np[lane];
        #pragma unroll
        for (int o = 16; o > 0; o >>= 1) {
            pl += __shfl_down_sync(0xffffffffu, pl, o);
            np += __shfl_down_sync(0xffffffffu, np, o);
        }
        if (lane == 0) {
            atomicAdd(&g_s.part[0], pl);
            atomicAdd(&g_s.part[1], np);
            __threadfence();
            unsigned done = atomicAdd(&g_s.done, 1u);
            if (done == gridDim.x - 1) {
                volatile float* p = g_s.part;
                float a = p[0];
                float b = p[1];
                out[0] = a / fmaxf(b, 1.0f);
            }
        }
    }
}

extern "C" void kernel_launch(void* const* d_in, const int* in_sizes, int n_in,
                              void* d_out, int out_size) {
    const float* pos = (const float*)d_in[0];
    const int*   ei  = (const int*)d_in[2];
    int N = in_sizes[0] / 2;      // node_positions: (1, N, 2)
    int E = in_sizes[2] / 2;      // edge_index: (2, E)

    static bool configured = false;
    if (!configured) {
        cudaFuncSetAttribute(edge_kernel,
                             cudaFuncAttributePreferredSharedMemoryCarveout, 0);
        configured = true;
    }

    void* scratch_ptr = nullptr;
    cudaGetSymbolAddress(&scratch_ptr, g_s);
    cudaMemsetAsync(scratch_ptr, 0, sizeof(Scratch));  // captured memset node

    const int TB = 256;
    edge_kernel<<<(E + TB - 1) / TB, TB>>>(pos, ei, E);
    node_kernel<<<NODE_GRID, NODE_TB>>>(N, (float*)d_out);
}